// round 15
// baseline (speedup 1.0000x reference)
#include <cuda_runtime.h>
#include <cuda_bf16.h>

// Problem constants
#define BB 8
#define LL 8192
#define DD 512
#define SF 4
#define RR 32                 // rows per chunk
#define CH (LL / RR)          // 256 chunks per batch
#define NCHUNK (BB * CH)      // 2048 total chunks
#define OUT_L (LL / SF)       // 2048
#define D4 (DD / 4)           // 128 float4 lanes
#define OUTG (RR / SF)        // 8 output rows per chunk
#define NSUP 16               // supers per batch
#define SUPC (CH / NSUP)      // 16 chunks per super
#define GRIDN 1024            // blocks; x 256 threads = 2048 chunk-workers
#define TPB 256               // two 128-thread chunk workers per block

// Scratch (L2-resident)
__device__ float g_part[BB][CH][DD];        // per-chunk aggregates (4 MB)
__device__ float g_sup[BB][NSUP][DD];       // per-super sums (256 KB)
__device__ unsigned g_bar;                  // monotonic barrier counter
__device__ unsigned g_done;                 // end-of-kernel cleanup counter

__device__ __forceinline__ unsigned ld_acq_u(const unsigned* p) {
    unsigned v;
    asm volatile("ld.acquire.gpu.u32 %0, [%1];" : "=r"(v) : "l"(p) : "memory");
    return v;
}

// Grid barrier: safe because launch_bounds(256,7) gives 7 blocks/SM capacity
// (56 warps, regs<=36, smem 0); 1024 <= 148*7 = 1036, all blocks co-resident.
__device__ __forceinline__ void gsync(unsigned target) {
    __syncthreads();
    if (threadIdx.x == 0) {
        __threadfence();                       // release prior writes
        atomicAdd(&g_bar, 1u);
        while (ld_acq_u(&g_bar) < target) __nanosleep(128);
    }
    __syncthreads();
    __threadfence();                           // acquire others' writes
}

__global__ __launch_bounds__(TPB, 7) void k_all(const float* __restrict__ x,
                                                float* __restrict__ out) {
    const int tid = threadIdx.x;
    const int h = tid >> 7;            // which chunk-worker (0/1)
    const int d4 = tid & 127;          // lane within worker
    const int t = blockIdx.x * 2 + h;  // chunk id 0..2047
    const int b = t >> 8;
    const int c = t & (CH - 1);

    const float4* xp = reinterpret_cast<const float4*>(
        x + ((size_t)b * LL + (size_t)c * RR) * DD) + d4;
    float4* op = reinterpret_cast<float4*>(
        out + ((size_t)b * OUT_L + (size_t)c * OUTG) * DD) + d4;

    // ── Phase A: local chunk scan; unscaled partials -> out, agg -> g_part ──
    float4 acc = make_float4(0.f, 0.f, 0.f, 0.f);
#pragma unroll
    for (int g = 0; g < OUTG; ++g) {
        float4 v0 = __ldcs(xp + (size_t)(g * SF + 0) * D4);
        float4 v1 = __ldcs(xp + (size_t)(g * SF + 1) * D4);
        float4 v2 = __ldcs(xp + (size_t)(g * SF + 2) * D4);
        float4 v3 = __ldcs(xp + (size_t)(g * SF + 3) * D4);
        acc.x += (v0.x + v1.x) + (v2.x + v3.x);
        acc.y += (v0.y + v1.y) + (v2.y + v3.y);
        acc.z += (v0.z + v1.z) + (v2.z + v3.z);
        acc.w += (v0.w + v1.w) + (v2.w + v3.w);
        op[(size_t)g * D4] = acc;              // unscaled partial prefix
    }
    reinterpret_cast<float4*>(g_part[b][c])[d4] = acc;

    gsync(GRIDN);

    // ── Phase B: super sums (128 super-tasks over blocks 0..63, both halves) ──
    if (blockIdx.x < (BB * NSUP) / 2) {
        const int task = blockIdx.x * 2 + h;   // 0..127
        const int sb = task >> 4;
        const int s = task & (NSUP - 1);
        float4 sum = make_float4(0.f, 0.f, 0.f, 0.f);
#pragma unroll
        for (int k = 0; k < SUPC; ++k) {
            float4 v = reinterpret_cast<const float4*>(g_part[sb][s * SUPC + k])[d4];
            sum.x += v.x; sum.y += v.y; sum.z += v.z; sum.w += v.w;
        }
        reinterpret_cast<float4*>(g_sup[sb][s])[d4] = sum;
    }

    gsync(2u * GRIDN);

    // ── Phase C: base from hierarchy (L2-hot), rewrite out in place ──
    {
        const int s = c >> 4;
        const int nin = c & (SUPC - 1);
        float4 base = make_float4(0.f, 0.f, 0.f, 0.f);
        for (int j = 0; j < s; ++j) {
            float4 v = reinterpret_cast<const float4*>(g_sup[b][j])[d4];
            base.x += v.x; base.y += v.y; base.z += v.z; base.w += v.w;
        }
        for (int j = 0; j < nin; ++j) {
            float4 v = reinterpret_cast<const float4*>(g_part[b][s * SUPC + j])[d4];
            base.x += v.x; base.y += v.y; base.z += v.z; base.w += v.w;
        }

#pragma unroll
        for (int g = 0; g < OUTG; ++g) {
            const float inv = 1.0f / (float)(c * RR + g * SF + SF);
            float4 v = op[(size_t)g * D4];      // L2 hit: written this kernel
            v.x = (v.x + base.x) * inv;
            v.y = (v.y + base.y) * inv;
            v.z = (v.z + base.z) * inv;
            v.w = (v.w + base.w) * inv;
            op[(size_t)g * D4] = v;
        }
    }

    // ── Cleanup: last block resets counters for the next graph replay ──
    __syncthreads();
    if (tid == 0) {
        __threadfence();
        unsigned v = atomicAdd(&g_done, 1u);
        if (v == GRIDN - 1) {
            g_bar = 0u; g_done = 0u;
            __threadfence();
        }
    }
}

extern "C" void kernel_launch(void* const* d_in, const int* in_sizes, int n_in,
                              void* d_out, int out_size) {
    const float* x = (const float*)d_in[0];
    float* out = (float*)d_out;

    k_all<<<GRIDN, TPB>>>(x, out);
}

// round 16
// speedup vs baseline: 1.0550x; 1.0550x over previous
#include <cuda_runtime.h>
#include <cuda_bf16.h>

// Problem constants
#define BB 8
#define LL 8192
#define DD 512
#define SF 4
#define RR 32                 // rows per chunk
#define CH (LL / RR)          // 256 chunks per batch
#define NCHUNK (BB * CH)      // 2048 total chunks
#define OUT_L (LL / SF)       // 2048
#define D4 (DD / 4)           // 128 float4 lanes
#define OUTG (RR / SF)        // 8 output rows per chunk
#define NSUP 16               // supers per batch
#define SUPC (CH / NSUP)      // 16 chunks per super
#define GRIDN 1024            // R9 geometry: all co-resident at 8 blocks/SM
#define CPB (NCHUNK / GRIDN)  // 2 chunks per block (uniform)

// Scratch (L2-resident)
__device__ float g_part[BB][CH][DD];        // per-chunk aggregates (4 MB)
__device__ float g_sup[BB][NSUP][DD];       // per-super sums (256 KB)
__device__ float g_base[BB][CH][DD];        // per-chunk exclusive bases (4 MB)
__device__ unsigned g_bar;                  // monotonic barrier counter
__device__ unsigned g_done;                 // end-of-kernel cleanup counter

__device__ __forceinline__ unsigned ld_acq_u(const unsigned* p) {
    unsigned v;
    asm volatile("ld.acquire.gpu.u32 %0, [%1];" : "=r"(v) : "l"(p) : "memory");
    return v;
}

// Grid barrier: safe because launch_bounds(128,8) gives 8 blocks/SM capacity
// (regs<=64, smem 0); 1024 <= 148*8 = 1184, all blocks co-resident.
__device__ __forceinline__ void gsync(unsigned target) {
    __syncthreads();
    if (threadIdx.x == 0) {
        __threadfence();                       // release prior writes
        atomicAdd(&g_bar, 1u);
        while (ld_acq_u(&g_bar) < target) __nanosleep(128);
    }
    __syncthreads();
    __threadfence();                           // acquire others' writes
}

__global__ __launch_bounds__(128, 8) void k_all(const float* __restrict__ x,
                                                float* __restrict__ out) {
    const int tid = threadIdx.x;
    const int d4 = tid;
    const int bid = blockIdx.x;

    // ── Phase A: two uniform chunk scans; unscaled partials -> out ──
#pragma unroll
    for (int u = 0; u < CPB; ++u) {
        const int t = bid * CPB + u;
        const int b = t >> 8;
        const int c = t & (CH - 1);
        const float4* xp = reinterpret_cast<const float4*>(
            x + ((size_t)b * LL + (size_t)c * RR) * DD) + d4;
        float4* op = reinterpret_cast<float4*>(
            out + ((size_t)b * OUT_L + (size_t)c * OUTG) * DD) + d4;

        float4 acc = make_float4(0.f, 0.f, 0.f, 0.f);
#pragma unroll
        for (int g = 0; g < OUTG; ++g) {
            float4 v0 = __ldcs(xp + (size_t)(g * SF + 0) * D4);
            float4 v1 = __ldcs(xp + (size_t)(g * SF + 1) * D4);
            float4 v2 = __ldcs(xp + (size_t)(g * SF + 2) * D4);
            float4 v3 = __ldcs(xp + (size_t)(g * SF + 3) * D4);
            acc.x += (v0.x + v1.x) + (v2.x + v3.x);
            acc.y += (v0.y + v1.y) + (v2.y + v3.y);
            acc.z += (v0.z + v1.z) + (v2.z + v3.z);
            acc.w += (v0.w + v1.w) + (v2.w + v3.w);
            op[(size_t)g * D4] = acc;          // unscaled partial prefix
        }
        reinterpret_cast<float4*>(g_part[b][c])[d4] = acc;
    }

    gsync(GRIDN);

    // ── Phase B1: super sums (blocks 0..127) ──
    if (bid < BB * NSUP) {
        const int b = bid >> 4;
        const int s = bid & (NSUP - 1);
        float4 sum = make_float4(0.f, 0.f, 0.f, 0.f);
#pragma unroll
        for (int k = 0; k < SUPC; ++k) {
            float4 v = reinterpret_cast<const float4*>(g_part[b][s * SUPC + k])[d4];
            sum.x += v.x; sum.y += v.y; sum.z += v.z; sum.w += v.w;
        }
        reinterpret_cast<float4*>(g_sup[b][s])[d4] = sum;
    }

    gsync(2u * GRIDN);

    // ── Phase B2: materialize per-chunk exclusive bases (blocks 0..127) ──
    if (bid < BB * NSUP) {
        const int b = bid >> 4;
        const int s = bid & (NSUP - 1);
        float4 run = make_float4(0.f, 0.f, 0.f, 0.f);
        for (int j = 0; j < s; ++j) {
            float4 v = reinterpret_cast<const float4*>(g_sup[b][j])[d4];
            run.x += v.x; run.y += v.y; run.z += v.z; run.w += v.w;
        }
#pragma unroll
        for (int k = 0; k < SUPC; ++k) {
            const int c = s * SUPC + k;
            reinterpret_cast<float4*>(g_base[b][c])[d4] = run;
            float4 v = reinterpret_cast<const float4*>(g_part[b][c])[d4];
            run.x += v.x; run.y += v.y; run.z += v.z; run.w += v.w;
        }
    }

    gsync(3u * GRIDN);

    // ── Phase C: tiny base read + in-place RMW of out (L2-resident) ──
#pragma unroll
    for (int u = 0; u < CPB; ++u) {
        const int t = bid * CPB + u;
        const int b = t >> 8;
        const int c = t & (CH - 1);
        const float4 base = reinterpret_cast<const float4*>(g_base[b][c])[d4];
        float4* op = reinterpret_cast<float4*>(
            out + ((size_t)b * OUT_L + (size_t)c * OUTG) * DD) + d4;
#pragma unroll
        for (int g = 0; g < OUTG; ++g) {
            const float inv = 1.0f / (float)(c * RR + g * SF + SF);
            float4 v = op[(size_t)g * D4];
            v.x = (v.x + base.x) * inv;
            v.y = (v.y + base.y) * inv;
            v.z = (v.z + base.z) * inv;
            v.w = (v.w + base.w) * inv;
            op[(size_t)g * D4] = v;
        }
    }

    // ── Cleanup: last block resets counters for the next graph replay ──
    __syncthreads();
    if (tid == 0) {
        __threadfence();
        unsigned v = atomicAdd(&g_done, 1u);
        if (v == GRIDN - 1) {
            g_bar = 0u; g_done = 0u;
            __threadfence();
        }
    }
}

extern "C" void kernel_launch(void* const* d_in, const int* in_sizes, int n_in,
                              void* d_out, int out_size) {
    const float* x = (const float*)d_in[0];
    float* out = (float*)d_out;

    k_all<<<GRIDN, 128>>>(x, out);
}